// round 2
// baseline (speedup 1.0000x reference)
#include <cuda_runtime.h>

// Shapes (fixed by the problem)
#define B_    16
#define DCH   512
#define HH    64
#define WW    64
#define HW    4096            // HH*WW
#define NROWS 65536           // B_*HW
#define KCB   1024
#define ZQ_ELEMS 33554432     // B_*DCH*HW
#define LOSS_OFF 33554432
#define PROB_OFF 33554433

__device__ float g_cnorm[KCB];
__device__ float g_znorm[NROWS];
__device__ int   g_minidx[NROWS];
__device__ float g_partial[2048];

// ---------------------------------------------------------------------------
// cnorm[j] = sum_k c[j][k]^2, sequential fp32 (replicates reference rounding)
// ---------------------------------------------------------------------------
__global__ void k_cnorm(const float* __restrict__ cb) {
    int j = blockIdx.x * blockDim.x + threadIdx.x;
    if (j >= KCB) return;
    const float* r = cb + (size_t)j * DCH;
    float acc = 0.f;
    for (int k = 0; k < DCH; ++k) {
        float v = r[k];
        acc = __fadd_rn(acc, __fmul_rn(v, v));
    }
    g_cnorm[j] = acc;
}

// ---------------------------------------------------------------------------
// znorm[i] = sum_k z_flat[i][k]^2, sequential fp32 over d (strided reads)
// z layout (b, d, h, w); row i = (bi, hi, wi)
// ---------------------------------------------------------------------------
__global__ void k_znorm(const float* __restrict__ z) {
    int i = blockIdx.x * blockDim.x + threadIdx.x;
    if (i >= NROWS) return;
    int bi  = i >> 12;
    int rem = i & 4095;
    const float* p = z + (size_t)bi * (DCH * HW) + rem;
    float acc = 0.f;
    for (int k = 0; k < DCH; ++k) {
        float v = p[(size_t)k * HW];
        acc = __fadd_rn(acc, __fmul_rn(v, v));
    }
    g_znorm[i] = acc;
}

// ---------------------------------------------------------------------------
// Main fused kernel: per block 32 rows x all 1024 codes.
//   dot = z . c  (fp32 register-blocked GEMM, smem-staged)
//   dist = fl(fl(zn + cn) - 2*dot)     <-- replicates reference rounding
//   argmin (first-index tie-break), softmax(-2*dist), write distance_prob
// 512 threads: rg = tid/64 (8 row groups x 4 rows), cg = tid%64 (16 cols ea.)
// ---------------------------------------------------------------------------
__global__ __launch_bounds__(512, 1)
void k_main(const float* __restrict__ z, const float* __restrict__ cb,
            float* __restrict__ prob) {
    __shared__ float s_cn[KCB];
    __shared__ float s_zn[32];
    // union region: GEMM phase uses cb tile (1024 x 9 pad) + z tile (8 x 32)
    //               reduce phase uses rv[32][64] (float) + ri[32][64] (int)
    __shared__ float sbuf[9472];   // 37,888 B

    float* cbS = sbuf;                                  // [1024*9]
    float (*zsS)[32] = (float (*)[32])(sbuf + 9216);    // [8][32]
    float (*rvS)[64] = (float (*)[64])sbuf;             // [32][64]
    int   (*riS)[64] = (int   (*)[64])(sbuf + 2048);    // [32][64]

    const int tid  = threadIdx.x;
    const int rg   = tid >> 6;
    const int cg   = tid & 63;
    const int row0 = blockIdx.x << 5;
    const int bi   = row0 >> 12;
    const int rem0 = row0 & 4095;

    s_cn[tid]       = g_cnorm[tid];
    s_cn[tid + 512] = g_cnorm[tid + 512];
    if (tid < 32) s_zn[tid] = g_znorm[row0 + tid];

    float acc[4][16];
#pragma unroll
    for (int r = 0; r < 4; ++r)
#pragma unroll
        for (int jj = 0; jj < 16; ++jj) acc[r][jj] = 0.f;

    const float* zbase = z + (size_t)bi * (DCH * HW) + rem0;

    for (int d0 = 0; d0 < DCH; d0 += 8) {
        __syncthreads();
        if (tid < 256) {
            int kk = tid >> 5, r = tid & 31;
            zsS[kk][r] = zbase[(size_t)(d0 + kk) * HW + r];
        }
#pragma unroll
        for (int q0 = 0; q0 < 4; ++q0) {
            int q = tid + q0 * 512;            // 0..2047
            int j = q >> 1, g = q & 1;
            float4 v = *(const float4*)(cb + (size_t)j * DCH + d0 + g * 4);
            float* dst = &cbS[j * 9 + g * 4];
            dst[0] = v.x; dst[1] = v.y; dst[2] = v.z; dst[3] = v.w;
        }
        __syncthreads();
#pragma unroll
        for (int kk = 0; kk < 8; ++kk) {
            float zr[4];
#pragma unroll
            for (int r = 0; r < 4; ++r) zr[r] = zsS[kk][(rg << 2) + r];
#pragma unroll
            for (int jj = 0; jj < 16; ++jj) {
                float c = cbS[(cg + (jj << 6)) * 9 + kk];
#pragma unroll
                for (int r = 0; r < 4; ++r)
                    acc[r][jj] = fmaf(zr[r], c, acc[r][jj]);
            }
        }
    }
    __syncthreads();

    // dist + local argmin
    float rowm[4];
#pragma unroll
    for (int r = 0; r < 4; ++r) {
        float zn = s_zn[(rg << 2) + r];
        float mv = 3.4e38f; int mi = 0x7fffffff;
#pragma unroll
        for (int jj = 0; jj < 16; ++jj) {
            int j = cg + (jj << 6);
            float A = __fadd_rn(zn, s_cn[j]);
            float d = __fadd_rn(A, __fmul_rn(-2.f, acc[r][jj]));
            acc[r][jj] = d;
            if (d < mv || (d == mv && j < mi)) { mv = d; mi = j; }
        }
        rvS[(rg << 2) + r][cg] = mv;
        riS[(rg << 2) + r][cg] = mi;
    }
    __syncthreads();
    for (int off = 32; off > 0; off >>= 1) {
        if (cg < off) {
#pragma unroll
            for (int r = 0; r < 4; ++r) {
                int row = (rg << 2) + r;
                float v1 = rvS[row][cg], v2 = rvS[row][cg + off];
                int   i1 = riS[row][cg], i2 = riS[row][cg + off];
                if (v2 < v1 || (v2 == v1 && i2 < i1)) {
                    rvS[row][cg] = v2; riS[row][cg] = i2;
                }
            }
        }
        __syncthreads();
    }
#pragma unroll
    for (int r = 0; r < 4; ++r) rowm[r] = rvS[(rg << 2) + r][0];
    if (cg == 0) {
#pragma unroll
        for (int r = 0; r < 4; ++r)
            g_minidx[row0 + (rg << 2) + r] = riS[(rg << 2) + r][0];
    }
    __syncthreads();

    // softmax: logit = -2*dist (exact), shift by row max = -2*rowmin
#pragma unroll
    for (int r = 0; r < 4; ++r) {
        float tmax = __fmul_rn(-2.f, rowm[r]);
        float s = 0.f;
#pragma unroll
        for (int jj = 0; jj < 16; ++jj) {
            float x = __fmul_rn(-2.f, acc[r][jj]);
            float e = __expf(__fsub_rn(x, tmax));
            acc[r][jj] = e;
            s += e;
        }
        rvS[(rg << 2) + r][cg] = s;
    }
    __syncthreads();
    for (int off = 32; off > 0; off >>= 1) {
        if (cg < off) {
#pragma unroll
            for (int r = 0; r < 4; ++r) {
                int row = (rg << 2) + r;
                rvS[row][cg] += rvS[row][cg + off];
            }
        }
        __syncthreads();
    }
#pragma unroll
    for (int r = 0; r < 4; ++r) {
        int row = (rg << 2) + r;
        float inv = 1.0f / rvS[row][0];
        float* op = prob + (size_t)(row0 + row) * KCB;
#pragma unroll
        for (int jj = 0; jj < 16; ++jj)
            op[cg + (jj << 6)] = acc[r][jj] * inv;
    }
}

// ---------------------------------------------------------------------------
// Gather z_q = codebook[min_idx] back to (b,d,h,w) layout + loss partials.
// Block = 32 rows (consecutive wi), stage 32 code rows in smem so both the
// codebook reads and the (b,d,h,w) writes are coalesced.
// ---------------------------------------------------------------------------
__global__ void k_gather(const float* __restrict__ z,
                         const float* __restrict__ cb,
                         float* __restrict__ outzq) {
    __shared__ float cbuf[32 * 257];
    __shared__ int   s_idx[32];
    __shared__ float sred[256];
    const int tid  = threadIdx.x;
    const int row0 = blockIdx.x << 5;
    const int bi   = row0 >> 12;
    const int rem0 = row0 & 4095;
    if (tid < 32) s_idx[tid] = g_minidx[row0 + tid];
    float lsum = 0.f;
    const size_t zb = (size_t)bi * (DCH * HW) + rem0;

    for (int half = 0; half < 2; ++half) {
        __syncthreads();
        int dbase = half << 8;
        for (int it = 0; it < 32; ++it)
            cbuf[it * 257 + tid] = cb[(size_t)s_idx[it] * DCH + dbase + tid];
        __syncthreads();
        for (int it = 0; it < 32; ++it) {
            int l    = tid + (it << 8);
            int rloc = l & 31;
            int dloc = l >> 5;
            size_t gi = zb + (size_t)(dbase + dloc) * HW + rloc;
            float c  = cbuf[rloc * 257 + dloc];
            float zv = z[gi];
            float df = c - zv;
            lsum += df * df;
            outzq[gi] = c;
        }
    }
    sred[tid] = lsum;
    __syncthreads();
    for (int off = 128; off > 0; off >>= 1) {
        if (tid < off) sred[tid] += sred[tid + off];
        __syncthreads();
    }
    if (tid == 0) g_partial[blockIdx.x] = sred[0];
}

// ---------------------------------------------------------------------------
// Deterministic final loss reduce: q_loss = 1.25 * mean((z_q - z)^2)
// (codebook_loss == commitment_loss numerically)
// ---------------------------------------------------------------------------
__global__ void k_loss(float* __restrict__ out) {
    __shared__ float s[1024];
    int tid = threadIdx.x;
    s[tid] = g_partial[tid] + g_partial[tid + 1024];
    __syncthreads();
    for (int off = 512; off > 0; off >>= 1) {
        if (tid < off) s[tid] += s[tid + off];
        __syncthreads();
    }
    if (tid == 0) out[0] = s[0] * (1.25f / 33554432.f);
}

// ---------------------------------------------------------------------------
extern "C" void kernel_launch(void* const* d_in, const int* in_sizes, int n_in,
                              void* d_out, int out_size) {
    const float* z  = (const float*)d_in[0];
    const float* cb = (const float*)d_in[1];
    float* out = (float*)d_out;

    k_cnorm<<<4, 256>>>(cb);
    k_znorm<<<256, 256>>>(z);
    k_main<<<2048, 512>>>(z, cb, out + PROB_OFF);
    k_gather<<<2048, 256>>>(z, cb, out);
    k_loss<<<1, 1024>>>(out + LOSS_OFF);
}

// round 4
// speedup vs baseline: 2.7613x; 2.7613x over previous
#include <cuda_runtime.h>
#include <cuda_bf16.h>
#include <cstdint>

#define DCH   512
#define HW    4096
#define NROWS 65536
#define KCB   1024
#define LOSS_OFF 33554432
#define PROB_OFF 33554433

// ---------------- device scratch ----------------
__device__ float g_cnorm[KCB];
__device__ float g_znorm[NROWS];
__device__ int   g_minidx[NROWS];
__device__ float g_partial[2048];
__device__ __nv_bfloat16 g_zhi[(size_t)NROWS * DCH];
__device__ __nv_bfloat16 g_zlo[(size_t)NROWS * DCH];
__device__ __nv_bfloat16 g_chi[(size_t)KCB * DCH];
__device__ __nv_bfloat16 g_clo[(size_t)KCB * DCH];
__device__ float g_dist[(size_t)NROWS * KCB];

// ---------------- PTX helpers (sm_80-era, plain-target legal) ----------------
__device__ __forceinline__ uint32_t smem_u32(const void* p) {
    uint32_t a;
    asm("{ .reg .u64 t; cvta.to.shared.u64 t, %1; cvt.u32.u64 %0, t; }" : "=r"(a) : "l"(p));
    return a;
}
__device__ __forceinline__ void cpasync16(uint32_t s, const void* g) {
    asm volatile("cp.async.cg.shared.global [%0], [%1], 16;" :: "r"(s), "l"(g));
}
#define CP_COMMIT()  asm volatile("cp.async.commit_group;" ::: "memory")
#define CP_WAIT1()   asm volatile("cp.async.wait_group 1;" ::: "memory")
#define CP_WAIT0()   asm volatile("cp.async.wait_group 0;" ::: "memory")

#define LDSM_X4(r0, r1, r2, r3, addr)                                          \
    asm volatile("ldmatrix.sync.aligned.m8n8.x4.shared.b16 {%0,%1,%2,%3}, [%4];" \
                 : "=r"(r0), "=r"(r1), "=r"(r2), "=r"(r3) : "r"(addr))

#define MMA16816(d, a, b0, b1)                                                 \
    asm volatile("mma.sync.aligned.m16n8k16.row.col.f32.bf16.bf16.f32 "        \
                 "{%0,%1,%2,%3}, {%4,%5,%6,%7}, {%8,%9}, {%0,%1,%2,%3};"       \
                 : "+f"((d)[0]), "+f"((d)[1]), "+f"((d)[2]), "+f"((d)[3])      \
                 : "r"((a)[0]), "r"((a)[1]), "r"((a)[2]), "r"((a)[3]),         \
                   "r"(b0), "r"(b1))

// ---------------------------------------------------------------------------
// cnorm / znorm: sequential fp32 (replicates reference rounding)
// ---------------------------------------------------------------------------
__global__ void k_cnorm(const float* __restrict__ cb) {
    int j = blockIdx.x * blockDim.x + threadIdx.x;
    if (j >= KCB) return;
    const float* r = cb + (size_t)j * DCH;
    float acc = 0.f;
    for (int k = 0; k < DCH; ++k) {
        float v = r[k];
        acc = __fadd_rn(acc, __fmul_rn(v, v));
    }
    g_cnorm[j] = acc;
}

__global__ void k_znorm(const float* __restrict__ z) {
    int i = blockIdx.x * blockDim.x + threadIdx.x;
    if (i >= NROWS) return;
    int bi  = i >> 12;
    int rem = i & 4095;
    const float* p = z + (size_t)bi * (DCH * HW) + rem;
    float acc = 0.f;
    for (int k = 0; k < DCH; ++k) {
        float v = p[(size_t)k * HW];
        acc = __fadd_rn(acc, __fmul_rn(v, v));
    }
    g_znorm[i] = acc;
}

// ---------------------------------------------------------------------------
// codebook bf16 hi/lo split (row-major, coalesced)
// ---------------------------------------------------------------------------
__global__ void k_csplit(const float* __restrict__ cb) {
    int idx = blockIdx.x * blockDim.x + threadIdx.x;
    if (idx >= (KCB * DCH) / 2) return;
    float2 v = ((const float2*)cb)[idx];
    __nv_bfloat162 h = __floats2bfloat162_rn(v.x, v.y);
    float2 hf = make_float2(__bfloat162float(__low2bfloat16(h)),
                            __bfloat162float(__high2bfloat16(h)));
    __nv_bfloat162 l = __floats2bfloat162_rn(v.x - hf.x, v.y - hf.y);
    ((__nv_bfloat162*)g_chi)[idx] = h;
    ((__nv_bfloat162*)g_clo)[idx] = l;
}

// ---------------------------------------------------------------------------
// z bf16 hi/lo split with smem transpose
// ---------------------------------------------------------------------------
__global__ __launch_bounds__(256)
void k_zsplit(const float* __restrict__ z) {
    __shared__ float sm[64 * 65];
    const int tid  = threadIdx.x;
    const int bi   = blockIdx.x >> 6;
    const int rem0 = (blockIdx.x & 63) << 6;
    const float* zb = z + (size_t)bi * (DCH * HW) + rem0;

    for (int kt = 0; kt < 8; ++kt) {
        __syncthreads();
        int k0 = kt * 64;
#pragma unroll
        for (int it = 0; it < 16; ++it) {
            int li = it * 256 + tid;
            int r = li & 63, k = li >> 6;
            sm[k * 65 + r] = zb[(size_t)(k0 + k) * HW + r];
        }
        __syncthreads();
        int r  = tid >> 2;
        int kq = tid & 3;
        uint32_t hbuf[8], lbuf[8];
#pragma unroll
        for (int i = 0; i < 8; ++i) {
            float v0 = sm[(kq * 16 + 2 * i)     * 65 + r];
            float v1 = sm[(kq * 16 + 2 * i + 1) * 65 + r];
            __nv_bfloat162 h = __floats2bfloat162_rn(v0, v1);
            float h0 = __bfloat162float(__low2bfloat16(h));
            float h1 = __bfloat162float(__high2bfloat16(h));
            __nv_bfloat162 l = __floats2bfloat162_rn(v0 - h0, v1 - h1);
            hbuf[i] = *(uint32_t*)&h;
            lbuf[i] = *(uint32_t*)&l;
        }
        size_t base = ((size_t)(bi * 4096 + rem0 + r)) * DCH + k0 + kq * 16;
        *(uint4*)((char*)g_zhi + base * 2)      = *(uint4*)(hbuf);
        *(uint4*)((char*)g_zhi + base * 2 + 16) = *(uint4*)(hbuf + 4);
        *(uint4*)((char*)g_zlo + base * 2)      = *(uint4*)(lbuf);
        *(uint4*)((char*)g_zlo + base * 2 + 16) = *(uint4*)(lbuf + 4);
    }
}

// ---------------------------------------------------------------------------
// HMMA GEMM + dist. CTA 128x128, K-chunk 32, 3-term bf16 split,
// double-buffered cp.async, 80B-pitch smem (ldmatrix conflict-free).
// grid = 4096: blockIdx = rowblk*8 + nblk (L2 reuse of z tiles).
// ---------------------------------------------------------------------------
#define PITCH 80
#define T_A_HI 0
#define T_A_LO 10240
#define T_B_HI 20480
#define T_B_LO 30720
#define STAGE_BYTES 40960
#define S_CN  81920
#define S_ZN  82432
#define GEMM_SMEM 82944

__global__ __launch_bounds__(256, 1)
void k_gemm() {
    extern __shared__ char smem[];
    const uint32_t sb = smem_u32(smem);
    const int tid   = threadIdx.x;
    const int lane  = tid & 31;
    const int wid   = tid >> 5;
    const int wm    = wid & 3;          // 4 warps along M
    const int wn    = wid >> 2;         // 2 warps along N
    const int rowblk = blockIdx.x >> 3;
    const int nblk   = blockIdx.x & 7;
    const int row0   = rowblk << 7;
    const int n0     = nblk << 7;

    // staging thread mapping
    const int srow = tid >> 2;          // 0..63
    const int sch  = tid & 3;           // 16B chunk

    const char* gAh = (const char*)g_zhi + ((size_t)(row0 + srow) << 10) + sch * 16;
    const char* gAl = (const char*)g_zlo + ((size_t)(row0 + srow) << 10) + sch * 16;
    const char* gBh = (const char*)g_chi + ((size_t)(n0   + srow) << 10) + sch * 16;
    const char* gBl = (const char*)g_clo + ((size_t)(n0   + srow) << 10) + sch * 16;
    const uint32_t sOff = srow * PITCH + sch * 16;

#define LOAD_STAGE(stg, kc) do {                                               \
    uint32_t s0 = sb + (stg) * STAGE_BYTES + sOff;                             \
    size_t   go = (size_t)(kc) * 64;                                           \
    cpasync16(s0 + T_A_HI,              gAh + go);                             \
    cpasync16(s0 + T_A_HI + 64 * PITCH, gAh + go + (size_t)64 * 1024);         \
    cpasync16(s0 + T_A_LO,              gAl + go);                             \
    cpasync16(s0 + T_A_LO + 64 * PITCH, gAl + go + (size_t)64 * 1024);         \
    cpasync16(s0 + T_B_HI,              gBh + go);                             \
    cpasync16(s0 + T_B_HI + 64 * PITCH, gBh + go + (size_t)64 * 1024);         \
    cpasync16(s0 + T_B_LO,              gBl + go);                             \
    cpasync16(s0 + T_B_LO + 64 * PITCH, gBl + go + (size_t)64 * 1024);         \
    CP_COMMIT();                                                               \
} while (0)

    LOAD_STAGE(0, 0);

    // norms into smem
    float* s_cn = (float*)(smem + S_CN);
    float* s_zn = (float*)(smem + S_ZN);
    if (tid < 128) {
        s_cn[tid] = g_cnorm[n0 + tid];
        s_zn[tid] = g_znorm[row0 + tid];
    }

    float acc[2][8][4];
#pragma unroll
    for (int mi = 0; mi < 2; ++mi)
#pragma unroll
        for (int n8 = 0; n8 < 8; ++n8)
#pragma unroll
            for (int e = 0; e < 4; ++e) acc[mi][n8][e] = 0.f;

    // ldmatrix lane addressing (per warp)
    const int aRow = (lane & 15);
    const int aChk = (lane >> 4);
    const int bRow = (lane & 7) + ((lane >> 4) << 3);
    const int bChk = ((lane >> 3) & 1);

    for (int kc = 0; kc < 16; ++kc) {
        if (kc + 1 < 16) LOAD_STAGE((kc + 1) & 1, kc + 1);
        if (kc + 1 < 16) { CP_WAIT1(); } else { CP_WAIT0(); }
        __syncthreads();

        const uint32_t st = sb + (kc & 1) * STAGE_BYTES;
#pragma unroll
        for (int ks = 0; ks < 2; ++ks) {
            uint32_t ah[2][4], al[2][4];
#pragma unroll
            for (int mi = 0; mi < 2; ++mi) {
                uint32_t ad = st + (wm * 32 + mi * 16 + aRow) * PITCH
                            + (ks * 2 + aChk) * 16;
                LDSM_X4(ah[mi][0], ah[mi][1], ah[mi][2], ah[mi][3], ad + T_A_HI);
                LDSM_X4(al[mi][0], al[mi][1], al[mi][2], al[mi][3], ad + T_A_LO);
            }
#pragma unroll
            for (int g = 0; g < 4; ++g) {
                uint32_t bh[4], bl[4];
                uint32_t bd = st + (wn * 64 + g * 16 + bRow) * PITCH
                            + (ks * 2 + bChk) * 16;
                LDSM_X4(bh[0], bh[1], bh[2], bh[3], bd + T_B_HI);
                LDSM_X4(bl[0], bl[1], bl[2], bl[3], bd + T_B_LO);
#pragma unroll
                for (int mi = 0; mi < 2; ++mi) {
                    MMA16816(acc[mi][2 * g],     ah[mi], bh[0], bh[1]);
                    MMA16816(acc[mi][2 * g + 1], ah[mi], bh[2], bh[3]);
                    MMA16816(acc[mi][2 * g],     ah[mi], bl[0], bl[1]);
                    MMA16816(acc[mi][2 * g + 1], ah[mi], bl[2], bl[3]);
                    MMA16816(acc[mi][2 * g],     al[mi], bh[0], bh[1]);
                    MMA16816(acc[mi][2 * g + 1], al[mi], bh[2], bh[3]);
                }
            }
        }
        __syncthreads();
    }

    // epilogue: dist = fl(fl(zn+cn) - 2*dot), float2 stores
#pragma unroll
    for (int mi = 0; mi < 2; ++mi) {
        int rL = wm * 32 + mi * 16 + (lane >> 2);
        float znL = s_zn[rL], znH = s_zn[rL + 8];
#pragma unroll
        for (int n8 = 0; n8 < 8; ++n8) {
            int cloc = wn * 64 + n8 * 8 + (lane & 3) * 2;
            float cn0 = s_cn[cloc], cn1 = s_cn[cloc + 1];
            float* a = acc[mi][n8];
            float2 dl, dh;
            dl.x = __fadd_rn(__fadd_rn(znL, cn0), __fmul_rn(-2.f, a[0]));
            dl.y = __fadd_rn(__fadd_rn(znL, cn1), __fmul_rn(-2.f, a[1]));
            dh.x = __fadd_rn(__fadd_rn(znH, cn0), __fmul_rn(-2.f, a[2]));
            dh.y = __fadd_rn(__fadd_rn(znH, cn1), __fmul_rn(-2.f, a[3]));
            *(float2*)&g_dist[(size_t)(row0 + rL)     * 1024 + n0 + cloc] = dl;
            *(float2*)&g_dist[(size_t)(row0 + rL + 8) * 1024 + n0 + cloc] = dh;
        }
    }
#undef LOAD_STAGE
}

// ---------------------------------------------------------------------------
// k_prob: per-row argmin (first-index tie-break) + softmax + prob write
// ---------------------------------------------------------------------------
__global__ __launch_bounds__(256)
void k_prob(float* __restrict__ prob) {
    __shared__ float sval[4][64];
    __shared__ int   sidx[4][64];
    const int tid = threadIdx.x;
    const int rg  = tid >> 6;
    const int cl  = tid & 63;
    const int row = (blockIdx.x << 2) + rg;
    const size_t base = (size_t)row * 1024 + cl;

    float d[16];
    float mv = 3.4e38f; int mi = 0x7fffffff;
#pragma unroll
    for (int i = 0; i < 16; ++i) {
        d[i] = g_dist[base + 64 * i];
        int j = cl + 64 * i;
        if (d[i] < mv) { mv = d[i]; mi = j; }
    }
    sval[rg][cl] = mv; sidx[rg][cl] = mi;
    __syncthreads();
    for (int off = 32; off > 0; off >>= 1) {
        if (cl < off) {
            float v2 = sval[rg][cl + off]; int i2 = sidx[rg][cl + off];
            if (v2 < sval[rg][cl] || (v2 == sval[rg][cl] && i2 < sidx[rg][cl])) {
                sval[rg][cl] = v2; sidx[rg][cl] = i2;
            }
        }
        __syncthreads();
    }
    float m = sval[rg][0];
    if (cl == 0) g_minidx[row] = sidx[rg][0];
    __syncthreads();

    float e[16], s = 0.f;
#pragma unroll
    for (int i = 0; i < 16; ++i) {
        e[i] = __expf(__fmul_rn(-2.f, __fsub_rn(d[i], m)));
        s += e[i];
    }
    sval[rg][cl] = s;
    __syncthreads();
    for (int off = 32; off > 0; off >>= 1) {
        if (cl < off) sval[rg][cl] += sval[rg][cl + off];
        __syncthreads();
    }
    float invS = 1.0f / sval[rg][0];
    float* op = prob + base;
#pragma unroll
    for (int i = 0; i < 16; ++i)
        op[64 * i] = e[i] * invS;
}

// ---------------------------------------------------------------------------
// gather z_q + loss partials
// ---------------------------------------------------------------------------
__global__ void k_gather(const float* __restrict__ z,
                         const float* __restrict__ cb,
                         float* __restrict__ outzq) {
    __shared__ float cbuf[32 * 257];
    __shared__ int   s_idx[32];
    __shared__ float sred[256];
    const int tid  = threadIdx.x;
    const int row0 = blockIdx.x << 5;
    const int bi   = row0 >> 12;
    const int rem0 = row0 & 4095;
    if (tid < 32) s_idx[tid] = g_minidx[row0 + tid];
    float lsum = 0.f;
    const size_t zb = (size_t)bi * (DCH * HW) + rem0;

    for (int halfp = 0; halfp < 2; ++halfp) {
        __syncthreads();
        int dbase = halfp << 8;
        for (int it = 0; it < 32; ++it)
            cbuf[it * 257 + tid] = cb[(size_t)s_idx[it] * DCH + dbase + tid];
        __syncthreads();
        for (int it = 0; it < 32; ++it) {
            int l    = tid + (it << 8);
            int rloc = l & 31;
            int dloc = l >> 5;
            size_t gi = zb + (size_t)(dbase + dloc) * HW + rloc;
            float c  = cbuf[rloc * 257 + dloc];
            float zv = z[gi];
            float df = c - zv;
            lsum += df * df;
            outzq[gi] = c;
        }
    }
    sred[tid] = lsum;
    __syncthreads();
    for (int off = 128; off > 0; off >>= 1) {
        if (tid < off) sred[tid] += sred[tid + off];
        __syncthreads();
    }
    if (tid == 0) g_partial[blockIdx.x] = sred[0];
}

__global__ void k_loss(float* __restrict__ out) {
    __shared__ float s[1024];
    int tid = threadIdx.x;
    s[tid] = g_partial[tid] + g_partial[tid + 1024];
    __syncthreads();
    for (int off = 512; off > 0; off >>= 1) {
        if (tid < off) s[tid] += s[tid + off];
        __syncthreads();
    }
    if (tid == 0) out[0] = s[0] * (1.25f / 33554432.f);
}

// ---------------------------------------------------------------------------
extern "C" void kernel_launch(void* const* d_in, const int* in_sizes, int n_in,
                              void* d_out, int out_size) {
    const float* z  = (const float*)d_in[0];
    const float* cb = (const float*)d_in[1];
    float* out = (float*)d_out;

    cudaFuncSetAttribute(k_gemm, cudaFuncAttributeMaxDynamicSharedMemorySize, GEMM_SMEM);

    k_csplit<<<1024, 256>>>(cb);
    k_cnorm<<<4, 256>>>(cb);
    k_zsplit<<<1024, 256>>>(z);
    k_znorm<<<256, 256>>>(z);
    k_gemm<<<4096, 256, GEMM_SMEM>>>();
    k_prob<<<16384, 256>>>(out + PROB_OFF);
    k_gather<<<2048, 256>>>(z, cb, out);
    k_loss<<<1, 1024>>>(out + LOSS_OFF);
}